// round 3
// baseline (speedup 1.0000x reference)
#include <cuda_runtime.h>
#include <math.h>

#define BB 32
#define TT 4096
#define FF 256
#define KSEL 409            // max(1, int(4096*0.1))
#define NCHUNK 64
#define TCHUNK (TT/NCHUNK)  // 64 rows -> 64KB tile
#define TILE_BYTES (TCHUNK*FF*4)

__device__ float g_w[BB*TT];
__device__ float g_part[BB*NCHUNK*FF];

// ==== Kernel A: smem-staged fused dot + unnormalized weighted feature sum ====
// Phase 0: tile gmem->smem (pure float4 copy, max MLP).
// Phase 1: warp-per-row dots from smem, w = exp(tanh(.)-1) (shift by max=1).
// Phase 2: thread-per-feature weighted sum from smem.
__global__ void __launch_bounds__(256) kA(const float* __restrict__ x,
                                          const float* __restrict__ W,
                                          const float* __restrict__ bias) {
    extern __shared__ float4 tile4[];          // 64KB: 64 rows x 256 floats
    __shared__ float wsh[TCHUNK];
    const int c = blockIdx.x, b = blockIdx.y;
    const int tid = threadIdx.x;
    const int warp = tid >> 5, lane = tid & 31;

    const float4* xg4 = (const float4*)(x + ((size_t)b*TT + (size_t)c*TCHUNK) * FF);

    // phase 0: 4096 float4, 16 per thread
    #pragma unroll
    for (int i = 0; i < 16; i++)
        tile4[tid + i*256] = xg4[tid + i*256];

    const float4* wr = (const float4*)W;
    const float4 w0 = __ldg(&wr[lane]);
    const float4 w1 = __ldg(&wr[lane + 32]);
    const float bias0 = bias[0];
    __syncthreads();

    // phase 1: 8 rows per warp
    #pragma unroll
    for (int r = 0; r < 8; r++) {
        const int row = warp * 8 + r;
        float4 a0 = tile4[row*64 + lane];
        float4 a1 = tile4[row*64 + 32 + lane];
        float s = a0.x*w0.x + a0.y*w0.y + a0.z*w0.z + a0.w*w0.w
                + a1.x*w1.x + a1.y*w1.y + a1.z*w1.z + a1.w*w1.w;
        #pragma unroll
        for (int o = 16; o; o >>= 1) s += __shfl_xor_sync(0xffffffffu, s, o);
        if (lane == 0)
            wsh[row] = __expf(tanhf(s + bias0) - 1.0f);
    }
    __syncthreads();
    if (tid < TCHUNK) g_w[b*TT + c*TCHUNK + tid] = wsh[tid];

    // phase 2: thread-per-feature weighted sum from smem
    const float* tile = (const float*)tile4;
    float acc = 0.f;
    #pragma unroll 8
    for (int t = 0; t < TCHUNK; t++) acc += tile[t*FF + tid] * wsh[t];
    g_part[(b*NCHUNK + c)*FF + tid] = acc;
}

// ==== Kernel BCD: Z + exact k-th select + compaction + correction + output ====
__global__ void __launch_bounds__(512) kBCD(const float* __restrict__ x,
                                            float* __restrict__ out) {
    __shared__ float    red[512];
    __shared__ unsigned cnt[32];
    __shared__ unsigned wtot[16];
    __shared__ int      idx_sh[KSEL];
    __shared__ float    wv_sh[KSEL];
    __shared__ float4   acc_sh[512];
    const int b = blockIdx.x, tid = threadIdx.x;
    const int lane = tid & 31, wid = tid >> 5;

    // load weights, Z-sum
    unsigned key[8];
    float zsum = 0.f;
    #pragma unroll
    for (int i = 0; i < 8; i++) {
        float w = g_w[b*TT + tid + i*512];
        key[i] = __float_as_uint(w);       // w > 0: raw bits order-preserving
        zsum += w;
    }
    red[tid] = zsum;
    if (tid < 32) cnt[tid] = 0;
    __syncthreads();
    #pragma unroll
    for (int o = 256; o; o >>= 1) {
        if (tid < o) red[tid] += red[tid + o];
        __syncthreads();
    }
    const float invZ = 1.0f / red[0];

    // radix bisection for k-th largest key (w <= 1.0 -> bits 31,30 are 0)
    unsigned prefix = 0;
    for (int bit = 29; bit >= 0; bit--) {
        const unsigned test = prefix | (1u << bit);
        unsigned c = 0;
        #pragma unroll
        for (int i = 0; i < 8; i++) c += (key[i] >= test);
        c = __reduce_add_sync(0xffffffffu, c);
        if (lane == 0) atomicAdd(&cnt[bit], c);
        __syncthreads();
        if (cnt[bit] >= KSEL) prefix = test;   // unique slot/bit: no re-sync
    }

    // deterministic compaction of top-k (index, weight) into smem
    unsigned tc = 0;
    #pragma unroll
    for (int i = 0; i < 8; i++) tc += (key[i] >= prefix);
    unsigned inc = tc;
    #pragma unroll
    for (int o = 1; o < 32; o <<= 1) {
        unsigned v = __shfl_up_sync(0xffffffffu, inc, o);
        if (lane >= o) inc += v;
    }
    if (lane == 31) wtot[wid] = inc;
    __syncthreads();
    if (tid == 0) {
        unsigned s = 0;
        #pragma unroll
        for (int j = 0; j < 16; j++) { unsigned t = wtot[j]; wtot[j] = s; s += t; }
    }
    __syncthreads();
    unsigned pos = wtot[wid] + inc - tc;
    #pragma unroll
    for (int i = 0; i < 8; i++) {
        if (key[i] >= prefix) {
            if (pos < KSEL) {
                idx_sh[pos] = tid + i*512;
                wv_sh[pos]  = __uint_as_float(key[i]);
            }
            pos++;
        }
    }
    __syncthreads();

    // fused partial-sum + emphasis correction (float4 over features)
    const int f4 = tid & 63;       // float4 feature group (4 features)
    const int h  = tid >> 6;       // 0..7
    const float4* part4 = ((const float4*)g_part) + (size_t)b*NCHUNK*64 + f4;
    float4 a = make_float4(0.f, 0.f, 0.f, 0.f);
    #pragma unroll
    for (int c = h; c < NCHUNK; c += 8) {
        float4 v = part4[c*64];
        a.x += v.x; a.y += v.y; a.z += v.z; a.w += v.w;
    }
    const float4* xb4 = ((const float4*)(x + (size_t)b*TT*FF)) + f4;
    float4 ac = make_float4(0.f, 0.f, 0.f, 0.f);
    for (int p = h; p < KSEL; p += 8) {
        const float4 v = xb4[(size_t)idx_sh[p] * 64];
        const float wv = wv_sh[p];
        ac.x += v.x*wv; ac.y += v.y*wv; ac.z += v.z*wv; ac.w += v.w*wv;
    }
    a.x += 0.5f*ac.x; a.y += 0.5f*ac.y; a.z += 0.5f*ac.z; a.w += 0.5f*ac.w;
    acc_sh[tid] = a;
    __syncthreads();
    if (tid < 64) {
        float4 s = acc_sh[tid];
        #pragma unroll
        for (int j = 1; j < 8; j++) {
            float4 t = acc_sh[tid + j*64];
            s.x += t.x; s.y += t.y; s.z += t.z; s.w += t.w;
        }
        s.x *= invZ; s.y *= invZ; s.z *= invZ; s.w *= invZ;
        ((float4*)out)[b*64 + tid] = s;
    }
}

extern "C" void kernel_launch(void* const* d_in, const int* in_sizes, int n_in,
                              void* d_out, int out_size) {
    const float* x    = (const float*)d_in[0];
    const float* W    = (const float*)d_in[1];
    const float* bias = (const float*)d_in[2];
    float* out = (float*)d_out;

    cudaFuncSetAttribute(kA, cudaFuncAttributeMaxDynamicSharedMemorySize, TILE_BYTES);
    dim3 gA(NCHUNK, BB);
    kA<<<gA, 256, TILE_BYTES>>>(x, W, bias);
    kBCD<<<BB, 512>>>(x, out);
}

// round 4
// speedup vs baseline: 1.3545x; 1.3545x over previous
#include <cuda_runtime.h>
#include <math.h>

#define BB 32
#define TT 4096
#define FF 256
#define KSEL 409            // max(1, int(4096*0.1))
#define RPT 32              // rows per tile
#define NTILES 8            // tiles per block
#define NCHUNK 16           // TT / (RPT*NTILES)
#define NSLICE 16
#define SLICE 26            // ceil(409/16)
#define TILE_F4 (RPT*FF/4)  // 2048 float4 per tile

__device__ float g_w[BB*TT];
__device__ float g_part[BB*NCHUNK*FF];
__device__ float g_corr[BB*NSLICE*FF];
__device__ int   g_idx[BB*KSEL];
__device__ float g_wv[BB*KSEL];
__device__ float g_invZ[BB];

__device__ __forceinline__ void cp_async16(unsigned smem_addr, const void* gptr) {
    asm volatile("cp.async.cg.shared.global [%0], [%1], 16;"
                 :: "r"(smem_addr), "l"(gptr));
}
__device__ __forceinline__ void cp_commit() {
    asm volatile("cp.async.commit_group;");
}
template <int N>
__device__ __forceinline__ void cp_wait() {
    asm volatile("cp.async.wait_group %0;" :: "n"(N));
}

// ==== Kernel A: cp.async double-buffered dot + weighted-sum, one DRAM read ====
__global__ void __launch_bounds__(256) kA(const float* __restrict__ x,
                                          const float* __restrict__ W,
                                          const float* __restrict__ bias) {
    extern __shared__ float4 buf4[];        // 2 x 2048 float4 (64KB)
    __shared__ float wsh[2][RPT];
    const int cb = blockIdx.x, b = blockIdx.y;
    const int tid = threadIdx.x;
    const int warp = tid >> 5, lane = tid & 31;
    const unsigned sbase = (unsigned)__cvta_generic_to_shared(buf4);

    const float4* xg4 = (const float4*)(x + ((size_t)b*TT + (size_t)cb*RPT*NTILES) * FF);
    const int t0g = cb * RPT * NTILES;

    const float4* wr = (const float4*)W;
    const float4 w0 = __ldg(&wr[lane]);
    const float4 w1 = __ldg(&wr[lane + 32]);
    const float bias0 = bias[0];

    // prologue: copy tile 0 into buf 0
    #pragma unroll
    for (int i = 0; i < 8; i++)
        cp_async16(sbase + (unsigned)(tid + i*256)*16u, xg4 + tid + i*256);
    cp_commit();

    float acc = 0.f;
    #pragma unroll
    for (int t = 0; t < NTILES; t++) {
        const int cur = t & 1;
        if (t + 1 < NTILES) {
            const int nxt = (t + 1) & 1;
            const float4* src = xg4 + (size_t)(t + 1) * TILE_F4;
            #pragma unroll
            for (int i = 0; i < 8; i++)
                cp_async16(sbase + (unsigned)(nxt*TILE_F4 + tid + i*256)*16u,
                           src + tid + i*256);
            cp_commit();
            cp_wait<1>();
        } else {
            cp_wait<0>();
        }
        __syncthreads();

        // dot phase: 4 rows per warp
        const float4* tb = buf4 + cur * TILE_F4;
        #pragma unroll
        for (int r = 0; r < 4; r++) {
            const int row = warp * 4 + r;
            float4 a0 = tb[row*64 + lane];
            float4 a1 = tb[row*64 + 32 + lane];
            float s = a0.x*w0.x + a0.y*w0.y + a0.z*w0.z + a0.w*w0.w
                    + a1.x*w1.x + a1.y*w1.y + a1.z*w1.z + a1.w*w1.w;
            #pragma unroll
            for (int o = 16; o; o >>= 1) s += __shfl_xor_sync(0xffffffffu, s, o);
            if (lane == 0) {
                float wv = __expf(tanhf(s + bias0) - 1.0f);  // shift by max=1
                wsh[cur][row] = wv;
                g_w[b*TT + t0g + t*RPT + row] = wv;
            }
        }
        __syncthreads();

        // weighted-sum phase: thread-per-feature
        const float* tf = (const float*)tb;
        #pragma unroll 8
        for (int r = 0; r < RPT; r++) acc += tf[r*FF + tid] * wsh[cur][r];
        __syncthreads();   // protect buf before iter t+2 overwrites it
    }
    g_part[(b*NCHUNK + cb)*FF + tid] = acc;
}

// ==== Kernel B: Z + exact k-th largest + deterministic compaction ====
__global__ void __launch_bounds__(512) kB(void) {
    __shared__ float    red[512];
    __shared__ unsigned cnt[32];
    __shared__ unsigned wtot[16];
    const int b = blockIdx.x, tid = threadIdx.x;
    const int lane = tid & 31, wid = tid >> 5;

    unsigned key[8];
    float zsum = 0.f;
    #pragma unroll
    for (int i = 0; i < 8; i++) {
        float w = g_w[b*TT + tid + i*512];
        key[i] = __float_as_uint(w);       // w in (0.135,1]: bits order-preserving
        zsum += w;
    }
    red[tid] = zsum;
    if (tid < 32) cnt[tid] = 0;
    __syncthreads();
    #pragma unroll
    for (int o = 256; o; o >>= 1) {
        if (tid < o) red[tid] += red[tid + o];
        __syncthreads();
    }
    if (tid == 0) g_invZ[b] = 1.0f / red[0];

    // w in (e^-2, 1]: float bits 31,30=0 and 29..25=11111 -> bisect bits 24..0
    unsigned prefix = 0x3E000000u;
    for (int bit = 24; bit >= 0; bit--) {
        const unsigned test = prefix | (1u << bit);
        unsigned c = 0;
        #pragma unroll
        for (int i = 0; i < 8; i++) c += (key[i] >= test);
        c = __reduce_add_sync(0xffffffffu, c);
        if (lane == 0) atomicAdd(&cnt[bit], c);
        __syncthreads();
        if (cnt[bit] >= KSEL) prefix = test;   // unique counter per bit
    }

    // deterministic compaction of (index, weight) for key >= prefix
    unsigned tc = 0;
    #pragma unroll
    for (int i = 0; i < 8; i++) tc += (key[i] >= prefix);
    unsigned inc = tc;
    #pragma unroll
    for (int o = 1; o < 32; o <<= 1) {
        unsigned v = __shfl_up_sync(0xffffffffu, inc, o);
        if (lane >= o) inc += v;
    }
    if (lane == 31) wtot[wid] = inc;
    __syncthreads();
    if (tid == 0) {
        unsigned s = 0;
        #pragma unroll
        for (int j = 0; j < 16; j++) { unsigned t = wtot[j]; wtot[j] = s; s += t; }
    }
    __syncthreads();
    unsigned pos = wtot[wid] + inc - tc;
    #pragma unroll
    for (int i = 0; i < 8; i++) {
        if (key[i] >= prefix) {
            if (pos < KSEL) {
                g_idx[b*KSEL + pos] = tid + i*512;
                g_wv[b*KSEL + pos]  = __uint_as_float(key[i]);
            }
            pos++;
        }
    }
}

// ==== Kernel C: emphasis correction gather, wide grid ====
__global__ void __launch_bounds__(256) kC(const float* __restrict__ x) {
    __shared__ int   idx_sh[SLICE];
    __shared__ float w_sh[SLICE];
    const int s = blockIdx.x, b = blockIdx.y, f = threadIdx.x;
    const int p0 = s * SLICE;
    const int n  = min(KSEL - p0, SLICE);
    if (f < n) {
        idx_sh[f] = g_idx[b*KSEL + p0 + f];
        w_sh[f]   = g_wv[b*KSEL + p0 + f];
    }
    __syncthreads();
    const float* xb = x + (size_t)b * TT * FF + f;
    float acc = 0.f;
    #pragma unroll 4
    for (int p = 0; p < n; p++)
        acc += xb[(size_t)idx_sh[p] * FF] * w_sh[p];
    g_corr[(b*NSLICE + s)*FF + f] = acc;
}

// ==== Kernel D: combine + 1/Z -> out [B,1,F] ====
__global__ void __launch_bounds__(256) kD(float* __restrict__ out) {
    const int b = blockIdx.x, f = threadIdx.x;
    float s1 = 0.f, sc = 0.f;
    #pragma unroll
    for (int c = 0; c < NCHUNK; c++) s1 += g_part[(b*NCHUNK + c)*FF + f];
    #pragma unroll
    for (int s = 0; s < NSLICE; s++) sc += g_corr[(b*NSLICE + s)*FF + f];
    out[b*FF + f] = (s1 + 0.5f * sc) * g_invZ[b];
}

extern "C" void kernel_launch(void* const* d_in, const int* in_sizes, int n_in,
                              void* d_out, int out_size) {
    const float* x    = (const float*)d_in[0];
    const float* W    = (const float*)d_in[1];
    const float* bias = (const float*)d_in[2];
    float* out = (float*)d_out;

    static bool attr_set = false;
    if (!attr_set) {
        cudaFuncSetAttribute(kA, cudaFuncAttributeMaxDynamicSharedMemorySize,
                             2 * TILE_F4 * 16);
        attr_set = true;
    }
    dim3 gA(NCHUNK, BB);
    kA<<<gA, 256, 2 * TILE_F4 * 16>>>(x, W, bias);
    kB<<<BB, 512>>>();
    dim3 gC(NSLICE, BB);
    kC<<<gC, 256>>>(x);
    kD<<<BB, 256>>>(out);
}